// round 3
// baseline (speedup 1.0000x reference)
#include <cuda_runtime.h>

// SpectralConv1D: out = irfft( pad( rfft(x)[:, :32, :] @ W ) )
// Rewritten as two small dense trig transforms + tiny mix (only 32 modes live).
//
// B=64, S=4096, Cin=Cout=64, MODES=32.

#define S_TOT   4096
#define SMASK   4095
#define CIN     64
#define COUT    64
#define MODES   32
#define NB      64
#define CHUNKS  8
#define S_CHUNK 512
#define STAGE_A 64
#define STAGE_C 128

typedef unsigned long long ull;

// Scratch (no cudaMalloc allowed)
__device__ float2 g_tw[S_TOT];                       // (cos, sin)(2*pi*j/4096)
__device__ float2 g_Yp[CHUNKS][NB][MODES][CIN];      // split-K partials (Cr, Si)
__device__ float2 g_G[NB][MODES][COUT];              // mixed+scaled (Gc, Gs)

// ---- packed fp32x2 helpers (Blackwell) ----
__device__ __forceinline__ ull pack2(float lo, float hi) {
    ull r; asm("mov.b64 %0, {%1, %2};" : "=l"(r) : "f"(lo), "f"(hi)); return r;
}
__device__ __forceinline__ float2 unpk(ull v) {
    float2 r; asm("mov.b64 {%0, %1}, %2;" : "=f"(r.x), "=f"(r.y) : "l"(v)); return r;
}
__device__ __forceinline__ void fma2(ull &acc, ull a, ull b) {
    asm("fma.rn.f32x2 %0, %1, %2, %0;" : "+l"(acc) : "l"(a), "l"(b));
}

// ---- twiddle table: g_tw[j] = (cos, sin)(2*pi*j/4096) ----
__global__ void twiddle_init() {
    int j = blockIdx.x * blockDim.x + threadIdx.x;
    if (j < S_TOT) {
        float s, c;
        sincospif(j * (1.0f / 2048.0f), &s, &c);   // angle = pi * (j/2048)
        g_tw[j] = make_float2(c, s);
    }
}

// ---- Stage 1: Y[b,k,i] = Sum_s x[b,s,i] * (cos, sin)(2*pi*k*s/S), split-K ----
__global__ void __launch_bounds__(256) kA(const float* __restrict__ x) {
    __shared__ float  xs[STAGE_A][CIN];        // 16 KB
    __shared__ float2 t2[STAGE_A][MODES];      // 16 KB
    int b = blockIdx.y, ch = blockIdx.x, tid = threadIdx.x;
    int tx = tid & 15, ty = tid >> 4;
    int i0 = tx * 4, k0 = ty * 2;

    ull acc[2][4];
#pragma unroll
    for (int a = 0; a < 2; a++)
#pragma unroll
        for (int c = 0; c < 4; c++) acc[a][c] = 0ull;

    const float* xb = x + ((size_t)b * S_TOT + (size_t)ch * S_CHUNK) * CIN;

    for (int st = 0; st < S_CHUNK / STAGE_A; ++st) {
        // load x tile (64 x 64 f32, coalesced float4)
        const float4* src = (const float4*)(xb + st * STAGE_A * CIN);
        float4* dst = (float4*)xs;
#pragma unroll
        for (int t = 0; t < (STAGE_A * CIN / 4) / 256; ++t)
            dst[tid + t * 256] = src[tid + t * 256];
        // build twiddle tile for this s-window
        int sg0 = ch * S_CHUNK + st * STAGE_A;
#pragma unroll
        for (int t = 0; t < STAGE_A * MODES / 256; ++t) {
            int e = tid + t * 256;
            int s = e >> 5, k = e & 31;
            t2[s][k] = g_tw[((sg0 + s) * k) & SMASK];
        }
        __syncthreads();
#pragma unroll 4
        for (int s = 0; s < STAGE_A; ++s) {
            float4 xv = *(const float4*)&xs[s][i0];
            ulonglong2 tt = *(const ulonglong2*)&t2[s][k0];   // (c,s) of k0, k0+1
            ull xd0 = pack2(xv.x, xv.x), xd1 = pack2(xv.y, xv.y);
            ull xd2 = pack2(xv.z, xv.z), xd3 = pack2(xv.w, xv.w);
            fma2(acc[0][0], tt.x, xd0); fma2(acc[0][1], tt.x, xd1);
            fma2(acc[0][2], tt.x, xd2); fma2(acc[0][3], tt.x, xd3);
            fma2(acc[1][0], tt.y, xd0); fma2(acc[1][1], tt.y, xd1);
            fma2(acc[1][2], tt.y, xd2); fma2(acc[1][3], tt.y, xd3);
        }
        __syncthreads();
    }
#pragma unroll
    for (int kk = 0; kk < 2; kk++)
#pragma unroll
        for (int ii = 0; ii < 4; ii++)
            g_Yp[ch][b][k0 + kk][i0 + ii] = unpk(acc[kk][ii]);
}

// ---- Stage 2: mix channels with real kernel + fold irfft scale ----
__global__ void __launch_bounds__(64) kB(const float* __restrict__ W) {
    int k = blockIdx.x, b = blockIdx.y, o = threadIdx.x;
    __shared__ float2 cs[CIN];
    {   // reduce split-K partials (thread o handles channel i = o)
        float2 a = make_float2(0.f, 0.f);
#pragma unroll
        for (int c = 0; c < CHUNKS; ++c) {
            float2 v = g_Yp[c][b][k][o];
            a.x += v.x; a.y += v.y;
        }
        cs[o] = a;
    }
    __syncthreads();
    const float* Wk = W + (size_t)k * CIN * COUT + o;
    float gc = 0.f, gs = 0.f;
#pragma unroll 8
    for (int i = 0; i < CIN; ++i) {
        float w = Wk[i * COUT];
        float2 v = cs[i];
        gc = fmaf(v.x, w, gc);
        gs = fmaf(v.y, w, gs);
    }
    float a = (k == 0 ? 1.0f : 2.0f) * (1.0f / (float)S_TOT);
    g_G[b][k][o] = make_float2(gc * a, gs * a);
}

// ---- Stage 3: out[b,s,o] = Sum_k Gc*cos + Gs*sin ----
__global__ void __launch_bounds__(256) kC(float* __restrict__ out) {
    __shared__ float2 t2[MODES][STAGE_C];   // 32 KB, [k][s]
    __shared__ float2 gsh[MODES][COUT];     // 16 KB, (Gc, Gs)
    int b = blockIdx.y, sc = blockIdx.x, tid = threadIdx.x;
    int sg0 = sc * STAGE_C;
    {   // copy this batch's G (16 KB) into smem
        const ulonglong2* src = (const ulonglong2*)&g_G[b][0][0];
        ulonglong2* dst = (ulonglong2*)gsh;
#pragma unroll
        for (int t = 0; t < (MODES * COUT / 2) / 256; ++t)
            dst[tid + t * 256] = src[tid + t * 256];
    }
#pragma unroll
    for (int t = 0; t < MODES * STAGE_C / 256; ++t) {
        int e = tid + t * 256;
        int k = e >> 7, s = e & 127;
        t2[k][s] = g_tw[(k * (sg0 + s)) & SMASK];
    }
    __syncthreads();

    int tx = tid & 7, ty = tid >> 3;
    int o0 = tx * 8, s0 = ty * 4;
    ull acc[4][8];
#pragma unroll
    for (int a = 0; a < 4; a++)
#pragma unroll
        for (int c = 0; c < 8; c++) acc[a][c] = 0ull;

#pragma unroll 2
    for (int k = 0; k < MODES; ++k) {
        ulonglong2 ta = *(const ulonglong2*)&t2[k][s0];
        ulonglong2 tb = *(const ulonglong2*)&t2[k][s0 + 2];
        ulonglong2 ga = *(const ulonglong2*)&gsh[k][o0];
        ulonglong2 gb = *(const ulonglong2*)&gsh[k][o0 + 2];
        ulonglong2 gc = *(const ulonglong2*)&gsh[k][o0 + 4];
        ulonglong2 gd = *(const ulonglong2*)&gsh[k][o0 + 6];
        ull tt[4] = {ta.x, ta.y, tb.x, tb.y};
        ull gg[8] = {ga.x, ga.y, gb.x, gb.y, gc.x, gc.y, gd.x, gd.y};
#pragma unroll
        for (int ss = 0; ss < 4; ss++)
#pragma unroll
            for (int oo = 0; oo < 8; oo++)
                fma2(acc[ss][oo], tt[ss], gg[oo]);
    }

    float* ob = out + ((size_t)b * S_TOT + sg0) * COUT;
#pragma unroll
    for (int ss = 0; ss < 4; ss++) {
        float r[8];
#pragma unroll
        for (int oo = 0; oo < 8; oo++) {
            float2 v = unpk(acc[ss][oo]);
            r[oo] = v.x + v.y;   // cos-part + sin-part
        }
        float4* dst = (float4*)&ob[(s0 + ss) * COUT + o0];
        dst[0] = make_float4(r[0], r[1], r[2], r[3]);
        dst[1] = make_float4(r[4], r[5], r[6], r[7]);
    }
}

extern "C" void kernel_launch(void* const* d_in, const int* in_sizes, int n_in,
                              void* d_out, int out_size) {
    const float* x = (const float*)d_in[0];   // [64, 4096, 64]
    const float* W = (const float*)d_in[1];   // [32, 64, 64]
    float* out = (float*)d_out;               // [64, 4096, 64]
    (void)in_sizes; (void)n_in; (void)out_size;

    twiddle_init<<<16, 256>>>();
    kA<<<dim3(CHUNKS, NB), 256>>>(x);
    kB<<<dim3(MODES, NB), 64>>>(W);
    kC<<<dim3(S_TOT / STAGE_C, NB), 256>>>(out);
}

// round 5
// speedup vs baseline: 3.0283x; 3.0283x over previous
#include <cuda_runtime.h>

// SpectralConv1D: out = irfft( pad( rfft(x)[:, :32, :] @ W ) )
// Quad-folded trig transforms: mirror symmetry of cos/sin over
// {s, 2048-s, 2048+s, 4096-s} gives 4x FMA+smem reduction in both transforms.
// B=64, S=4096, Cin=Cout=64, MODES=32.

#define S_TOT   4096
#define SMASK   4095
#define CIN     64
#define COUT    64
#define MODES   32
#define NB      64
#define CH_A    8          // kA grid.x chunks
#define SUBS    4          // in-block s-subsets (extra split-K)
#define NCH     (CH_A*SUBS)
#define QPB_A   128        // quads per kA block
#define STG_A   16         // quads per kA stage
#define QPB_C   64         // quads per kC block

typedef unsigned long long ull;

// Scratch (no cudaMalloc allowed)
__device__ float2 g_tw[S_TOT];                      // (cos,sin)(2*pi*j/4096)
__device__ float2 g_Yp[NCH][NB][MODES][CIN];        // split-K partials (Cr,Si)
__device__ float2 g_G[NB][MODES][COUT];             // mixed+scaled (Gc,Gs)

// ---- packed fp32x2 helpers ----
__device__ __forceinline__ float2 unpk(ull v) {
    float2 r; asm("mov.b64 {%0, %1}, %2;" : "=f"(r.x), "=f"(r.y) : "l"(v)); return r;
}
__device__ __forceinline__ void fma2(ull &acc, ull a, ull b) {
    asm("fma.rn.f32x2 %0, %1, %2, %0;" : "+l"(acc) : "l"(a), "l"(b));
}

__global__ void twiddle_init() {
    int j = blockIdx.x * blockDim.x + threadIdx.x;
    if (j < S_TOT) {
        float s, c;
        sincospif(j * (1.0f / 2048.0f), &s, &c);
        g_tw[j] = make_float2(c, s);
    }
}

// ---- Stage 1 (quad-folded forward DFT) ----
// Cr_k += cos(th)*[P + (-1)^k Q],  Si_k += sin(th)*[R + (-1)^k T]
// P=x1+x4, Q=x2+x3, R=x1-x4, T=x3-x2  over quad {s,2048-s,2048+s,4096-s}, s=1..1024
__global__ void __launch_bounds__(256) kA(const float* __restrict__ x) {
    __shared__ float2 cmb[2][STG_A][CIN];   // [parity][s][i] = (Peff,Reff), 16 KB
    __shared__ float2 t2[STG_A][MODES];     // 4 KB
    int b = blockIdx.y, tid = threadIdx.x;
    int tx  = tid & 15;        // i in {tx, tx+16, tx+32, tx+48}
    int kg  = (tid >> 4) & 3;  // k0 = kg*8
    int sub = tid >> 6;        // s-subset 0..3
    int k0 = kg * 8;
    int q00 = blockIdx.x * QPB_A;

    ull acc[8][4];
#pragma unroll
    for (int a = 0; a < 8; a++)
#pragma unroll
        for (int c = 0; c < 4; c++) acc[a][c] = 0ull;

    const float* xb = x + (size_t)b * S_TOT * CIN;

    for (int st = 0; st < QPB_A / STG_A; ++st) {
        int q0 = q00 + st * STG_A;
        {   // load 4 mirror rows, combine into parity operands
            int r = tid >> 4, ig = tid & 15;
            int s = q0 + 1 + r;
            float4 a1 = *(const float4*)&xb[(size_t)s * CIN + ig * 4];
            float4 a2 = *(const float4*)&xb[(size_t)(2048 - s) * CIN + ig * 4];
            float4 a3 = *(const float4*)&xb[(size_t)(2048 + s) * CIN + ig * 4];
            float4 a4 = *(const float4*)&xb[(size_t)(4096 - s) * CIN + ig * 4];
            float h = (s == 1024) ? 0.5f : 1.0f;   // quad double-counts at s=1024
            float x1[4] = {a1.x, a1.y, a1.z, a1.w};
            float x2[4] = {a2.x, a2.y, a2.z, a2.w};
            float x3[4] = {a3.x, a3.y, a3.z, a3.w};
            float x4[4] = {a4.x, a4.y, a4.z, a4.w};
            float pe[4], re[4], po[4], ro[4];
#pragma unroll
            for (int j = 0; j < 4; ++j) {
                float P = x1[j] + x4[j], Q = x2[j] + x3[j];
                float R = x1[j] - x4[j], T = x3[j] - x2[j];
                pe[j] = h * (P + Q); re[j] = h * (R + T);
                po[j] = h * (P - Q); ro[j] = h * (R - T);
            }
            *(float4*)&cmb[0][r][ig * 4]     = make_float4(pe[0], re[0], pe[1], re[1]);
            *(float4*)&cmb[0][r][ig * 4 + 2] = make_float4(pe[2], re[2], pe[3], re[3]);
            *(float4*)&cmb[1][r][ig * 4]     = make_float4(po[0], ro[0], po[1], ro[1]);
            *(float4*)&cmb[1][r][ig * 4 + 2] = make_float4(po[2], ro[2], po[3], ro[3]);
        }
#pragma unroll
        for (int t = 0; t < 2; ++t) {       // twiddle tile
            int e = tid + t * 256;
            int sl = e >> 5, k = e & 31;
            t2[sl][k] = g_tw[((q0 + 1 + sl) * k) & SMASK];
        }
        __syncthreads();
#pragma unroll
        for (int slr = 0; slr < 4; ++slr) {
            int sl = sub * 4 + slr;
            ull cE[4], cO[4];
#pragma unroll
            for (int ii = 0; ii < 4; ++ii) {   // strided LDS.64: conflict-free
                cE[ii] = *(const ull*)&cmb[0][sl][tx + 16 * ii];
                cO[ii] = *(const ull*)&cmb[1][sl][tx + 16 * ii];
            }
            ull tt[8];
#pragma unroll
            for (int m = 0; m < 4; ++m) {
                ulonglong2 tp = *(const ulonglong2*)&t2[sl][k0 + 2 * m];
                tt[2 * m] = tp.x; tt[2 * m + 1] = tp.y;
            }
#pragma unroll
            for (int kk = 0; kk < 8; ++kk)
#pragma unroll
                for (int ii = 0; ii < 4; ++ii)
                    fma2(acc[kk][ii], tt[kk], (kk & 1) ? cO[ii] : cE[ii]);
        }
        __syncthreads();
    }
    int ch = blockIdx.x * SUBS + sub;
#pragma unroll
    for (int kk = 0; kk < 8; ++kk)
#pragma unroll
        for (int ii = 0; ii < 4; ++ii)
            g_Yp[ch][b][k0 + kk][tx + 16 * ii] = unpk(acc[kk][ii]);
}

// ---- Stage 2: reduce partials + leftover rows {0,2048} + channel mix ----
__global__ void __launch_bounds__(64) kB(const float* __restrict__ W,
                                         const float* __restrict__ x) {
    int k = blockIdx.x, b = blockIdx.y, o = threadIdx.x;
    __shared__ float2 cs[CIN];
    {
        float2 a = make_float2(0.f, 0.f);
#pragma unroll
        for (int c = 0; c < NCH; ++c) {
            float2 v = g_Yp[c][b][k][o];
            a.x += v.x; a.y += v.y;
        }
        // rows 0 and 2048: sin terms are 0; cos = 1 and (-1)^k
        float x0    = x[(size_t)b * S_TOT * CIN + o];
        float x2048 = x[(size_t)b * S_TOT * CIN + 2048 * CIN + o];
        a.x += x0 + ((k & 1) ? -x2048 : x2048);
        cs[o] = a;
    }
    __syncthreads();
    const float* Wk = W + (size_t)k * CIN * COUT + o;
    float gc = 0.f, gs = 0.f;
#pragma unroll 8
    for (int i = 0; i < CIN; ++i) {
        float w = Wk[i * COUT];
        float2 v = cs[i];
        gc = fmaf(v.x, w, gc);
        gs = fmaf(v.y, w, gs);
    }
    float a = (k == 0 ? 1.0f : 2.0f) * (1.0f / (float)S_TOT);
    g_G[b][k][o] = make_float2(gc * a, gs * a);
}

// ---- Stage 3 (quad-folded inverse): one fma2 per (s,k,o) -> 4 outputs ----
__global__ void __launch_bounds__(256) kC(float* __restrict__ out) {
    __shared__ float2 t2c[MODES][QPB_C];    // 16 KB, (cos,sin) per (k, s-local)
    __shared__ float2 gsh[MODES][COUT];     // 16 KB, (Gc,Gs)
    int b = blockIdx.y, tid = threadIdx.x;
    int q0 = blockIdx.x * QPB_C;            // s = q0+1+sl, sl in [0,64)
    {   // copy G for this batch
        const ulonglong2* src = (const ulonglong2*)&g_G[b][0][0];
        ulonglong2* dst = (ulonglong2*)gsh;
#pragma unroll
        for (int t = 0; t < (MODES * COUT / 2) / 256; ++t)
            dst[tid + t * 256] = src[tid + t * 256];
    }
#pragma unroll
    for (int t = 0; t < MODES * QPB_C / 256; ++t) {   // twiddles
        int e = tid + t * 256;
        int k = e >> 6, sl = e & 63;
        t2c[k][sl] = g_tw[((q0 + 1 + sl) * k) & SMASK];
    }
    __syncthreads();

    int tx = tid & 15, ty = tid >> 4;
    int s0 = ty * 4;                 // 4 consecutive s-locals
    ull acc[2][4][4];                // [parity][s][o]
#pragma unroll
    for (int p = 0; p < 2; p++)
#pragma unroll
        for (int a = 0; a < 4; a++)
#pragma unroll
            for (int c = 0; c < 4; c++) acc[p][a][c] = 0ull;

#pragma unroll
    for (int k = 0; k < MODES; ++k) {
        ulonglong2 ta = *(const ulonglong2*)&t2c[k][s0];
        ulonglong2 tb = *(const ulonglong2*)&t2c[k][s0 + 2];
        ull tt[4] = {ta.x, ta.y, tb.x, tb.y};
        ull gg[4];
#pragma unroll
        for (int oo = 0; oo < 4; ++oo)     // strided LDS.64: conflict-free
            gg[oo] = *(const ull*)&gsh[k][tx + 16 * oo];
        const int par = k & 1;
#pragma unroll
        for (int ss = 0; ss < 4; ++ss)
#pragma unroll
            for (int oo = 0; oo < 4; ++oo)
                fma2(acc[par][ss][oo], tt[ss], gg[oo]);
    }

    float* ob = out + (size_t)b * S_TOT * COUT;
#pragma unroll
    for (int ss = 0; ss < 4; ++ss) {
        int s = q0 + 1 + s0 + ss;
#pragma unroll
        for (int oo = 0; oo < 4; ++oo) {
            float2 E = unpk(acc[0][ss][oo]);   // (Ec, Es)
            float2 O = unpk(acc[1][ss][oo]);   // (Oc, Os)
            int o = tx + 16 * oo;
            ob[(size_t)s * COUT + o]            = E.x + E.y + O.x + O.y;
            ob[(size_t)(2048 - s) * COUT + o]   = E.x - E.y - O.x + O.y;
            ob[(size_t)(2048 + s) * COUT + o]   = E.x + E.y - O.x - O.y;
            ob[(size_t)(4096 - s) * COUT + o]   = E.x - E.y + O.x - O.y;
        }
    }
}

// ---- Stage 4: rows 0 and 2048 (sin terms vanish) ----
__global__ void __launch_bounds__(64) kD(float* __restrict__ out) {
    int b = blockIdx.x, o = threadIdx.x;
    float a0 = 0.f, a1 = 0.f;
#pragma unroll
    for (int k = 0; k < MODES; ++k) {
        float gc = g_G[b][k][o].x;
        a0 += gc;
        a1 += (k & 1) ? -gc : gc;
    }
    out[(size_t)b * S_TOT * COUT + o] = a0;
    out[(size_t)b * S_TOT * COUT + 2048 * COUT + o] = a1;
}

extern "C" void kernel_launch(void* const* d_in, const int* in_sizes, int n_in,
                              void* d_out, int out_size) {
    const float* x = (const float*)d_in[0];   // [64, 4096, 64]
    const float* W = (const float*)d_in[1];   // [32, 64, 64]
    float* out = (float*)d_out;               // [64, 4096, 64]
    (void)in_sizes; (void)n_in; (void)out_size;

    twiddle_init<<<16, 256>>>();
    kA<<<dim3(CH_A, NB), 256>>>(x);
    kB<<<dim3(MODES, NB), 64>>>(W, x);
    kC<<<dim3(1024 / QPB_C, NB), 256>>>(out);
    kD<<<NB, 64>>>(out);
}

// round 6
// speedup vs baseline: 3.1124x; 1.0278x over previous
#include <cuda_runtime.h>

// SpectralConv1D: out = irfft( pad( rfft(x)[:, :32, :] @ W ) )
// Quad-folded trig transforms (4x reduction via mirror symmetry over
// {s, 2048-s, 2048+s, 4096-s}). B=64, S=4096, Cin=Cout=64, MODES=32.

#define S_TOT   4096
#define SMASK   4095
#define CIN     64
#define COUT    64
#define MODES   32
#define NB      64
#define CH_A    4          // kA grid.x chunks
#define SUBS    4          // in-block s-subsets (extra split-K)
#define NCH     (CH_A*SUBS)
#define QPB_A   256        // quads per kA block
#define STG_A   16         // quads per kA stage
#define QPB_C   32         // quads per kC block

typedef unsigned long long ull;

// Scratch (no cudaMalloc allowed)
__device__ float2 g_tw[S_TOT];                      // (cos,sin)(2*pi*j/4096)
__device__ float2 g_Yp[NCH][NB][MODES][CIN];        // split-K partials (Cr,Si)
__device__ float2 g_G[NB][MODES][COUT];             // mixed+scaled (Gc,Gs)

// ---- packed fp32x2 helpers ----
__device__ __forceinline__ float2 unpk(ull v) {
    float2 r; asm("mov.b64 {%0, %1}, %2;" : "=f"(r.x), "=f"(r.y) : "l"(v)); return r;
}
__device__ __forceinline__ void fma2(ull &acc, ull a, ull b) {
    asm("fma.rn.f32x2 %0, %1, %2, %0;" : "+l"(acc) : "l"(a), "l"(b));
}

__global__ void twiddle_init() {
    int j = blockIdx.x * blockDim.x + threadIdx.x;
    if (j < S_TOT) {
        float s, c;
        sincospif(j * (1.0f / 2048.0f), &s, &c);
        g_tw[j] = make_float2(c, s);
    }
}

// ---- Stage 1 (quad-folded forward DFT) ----
// Cr_k += cos(th)*[P + (-1)^k Q],  Si_k += sin(th)*[R + (-1)^k T]
// P=x1+x4, Q=x2+x3, R=x1-x4, T=x3-x2  over quad {s,2048-s,2048+s,4096-s}, s=1..1024
__global__ void __launch_bounds__(256) kA(const float* __restrict__ x) {
    __shared__ float2 cmb[2][STG_A][CIN];   // [parity][s][i] = (Peff,Reff), 16 KB
    __shared__ float2 t2[STG_A][MODES];     // 4 KB
    int b = blockIdx.y, tid = threadIdx.x;
    int tx  = tid & 15;        // i in {tx, tx+16, tx+32, tx+48}
    int kg  = (tid >> 4) & 3;  // k0 = kg*8
    int sub = tid >> 6;        // s-subset 0..3
    int k0 = kg * 8;
    int q00 = blockIdx.x * QPB_A;

    ull acc[8][4];
#pragma unroll
    for (int a = 0; a < 8; a++)
#pragma unroll
        for (int c = 0; c < 4; c++) acc[a][c] = 0ull;

    const float* xb = x + (size_t)b * S_TOT * CIN;

    for (int st = 0; st < QPB_A / STG_A; ++st) {
        int q0 = q00 + st * STG_A;
        {   // load 4 mirror rows, combine into parity operands
            int r = tid >> 4, ig = tid & 15;
            int s = q0 + 1 + r;
            float4 a1 = *(const float4*)&xb[(size_t)s * CIN + ig * 4];
            float4 a2 = *(const float4*)&xb[(size_t)(2048 - s) * CIN + ig * 4];
            float4 a3 = *(const float4*)&xb[(size_t)(2048 + s) * CIN + ig * 4];
            float4 a4 = *(const float4*)&xb[(size_t)(4096 - s) * CIN + ig * 4];
            float h = (s == 1024) ? 0.5f : 1.0f;   // quad double-counts at s=1024
            float x1[4] = {a1.x, a1.y, a1.z, a1.w};
            float x2[4] = {a2.x, a2.y, a2.z, a2.w};
            float x3[4] = {a3.x, a3.y, a3.z, a3.w};
            float x4[4] = {a4.x, a4.y, a4.z, a4.w};
            float pe[4], re[4], po[4], ro[4];
#pragma unroll
            for (int j = 0; j < 4; ++j) {
                float P = x1[j] + x4[j], Q = x2[j] + x3[j];
                float R = x1[j] - x4[j], T = x3[j] - x2[j];
                pe[j] = h * (P + Q); re[j] = h * (R + T);
                po[j] = h * (P - Q); ro[j] = h * (R - T);
            }
            *(float4*)&cmb[0][r][ig * 4]     = make_float4(pe[0], re[0], pe[1], re[1]);
            *(float4*)&cmb[0][r][ig * 4 + 2] = make_float4(pe[2], re[2], pe[3], re[3]);
            *(float4*)&cmb[1][r][ig * 4]     = make_float4(po[0], ro[0], po[1], ro[1]);
            *(float4*)&cmb[1][r][ig * 4 + 2] = make_float4(po[2], ro[2], po[3], ro[3]);
        }
#pragma unroll
        for (int t = 0; t < 2; ++t) {       // twiddle tile
            int e = tid + t * 256;
            int sl = e >> 5, k = e & 31;
            t2[sl][k] = g_tw[((q0 + 1 + sl) * k) & SMASK];
        }
        __syncthreads();
#pragma unroll
        for (int slr = 0; slr < 4; ++slr) {
            int sl = sub * 4 + slr;
            ull cE[4], cO[4];
#pragma unroll
            for (int ii = 0; ii < 4; ++ii) {   // strided LDS.64: conflict-free
                cE[ii] = *(const ull*)&cmb[0][sl][tx + 16 * ii];
                cO[ii] = *(const ull*)&cmb[1][sl][tx + 16 * ii];
            }
            ull tt[8];
#pragma unroll
            for (int m = 0; m < 4; ++m) {
                ulonglong2 tp = *(const ulonglong2*)&t2[sl][k0 + 2 * m];
                tt[2 * m] = tp.x; tt[2 * m + 1] = tp.y;
            }
#pragma unroll
            for (int kk = 0; kk < 8; ++kk)
#pragma unroll
                for (int ii = 0; ii < 4; ++ii)
                    fma2(acc[kk][ii], tt[kk], (kk & 1) ? cO[ii] : cE[ii]);
        }
        __syncthreads();
    }
    int ch = blockIdx.x * SUBS + sub;
#pragma unroll
    for (int kk = 0; kk < 8; ++kk)
#pragma unroll
        for (int ii = 0; ii < 4; ++ii)
            g_Yp[ch][b][k0 + kk][tx + 16 * ii] = unpk(acc[kk][ii]);
}

// ---- Stage 2: reduce partials + leftover rows {0,2048} + channel mix ----
__global__ void __launch_bounds__(64) kB(const float* __restrict__ W,
                                         const float* __restrict__ x) {
    int k = blockIdx.x, b = blockIdx.y, o = threadIdx.x;
    __shared__ float2 cs[CIN];
    {
        float2 a = make_float2(0.f, 0.f);
#pragma unroll
        for (int c = 0; c < NCH; ++c) {
            float2 v = g_Yp[c][b][k][o];
            a.x += v.x; a.y += v.y;
        }
        // rows 0 and 2048: sin terms are 0; cos = 1 and (-1)^k
        float x0    = x[(size_t)b * S_TOT * CIN + o];
        float x2048 = x[(size_t)b * S_TOT * CIN + 2048 * CIN + o];
        a.x += x0 + ((k & 1) ? -x2048 : x2048);
        cs[o] = a;
    }
    __syncthreads();
    const float* Wk = W + (size_t)k * CIN * COUT + o;
    float gc = 0.f, gs = 0.f;
#pragma unroll 8
    for (int i = 0; i < CIN; ++i) {
        float w = Wk[i * COUT];
        float2 v = cs[i];
        gc = fmaf(v.x, w, gc);
        gs = fmaf(v.y, w, gs);
    }
    float a = (k == 0 ? 1.0f : 2.0f) * (1.0f / (float)S_TOT);
    g_G[b][k][o] = make_float2(gc * a, gs * a);
}

// ---- Stage 3 (quad-folded inverse): one fma2 per (s,k,o) -> 4 outputs ----
// Thread owns o in {2tx, 2tx+1, 2tx+32, 2tx+33}: contiguous LDS.128 operand
// reads and fully-coalesced STG.64 stores. Rows 0/2048 folded into block x==0.
__global__ void __launch_bounds__(256) kC(float* __restrict__ out) {
    __shared__ float2 t2c[MODES][QPB_C];    // 8 KB
    __shared__ float2 gsh[MODES][COUT];     // 16 KB
    int b = blockIdx.y, tid = threadIdx.x;
    int q0 = blockIdx.x * QPB_C;            // s = q0+1+sl, sl in [0,32)
    {   // copy G for this batch (16 KB)
        const ulonglong2* src = (const ulonglong2*)&g_G[b][0][0];
        ulonglong2* dst = (ulonglong2*)gsh;
#pragma unroll
        for (int t = 0; t < (MODES * COUT / 2) / 256; ++t)
            dst[tid + t * 256] = src[tid + t * 256];
    }
#pragma unroll
    for (int t = 0; t < MODES * QPB_C / 256; ++t) {   // twiddles
        int e = tid + t * 256;
        int k = e >> 5, sl = e & 31;
        t2c[k][sl] = g_tw[((q0 + 1 + sl) * k) & SMASK];
    }
    __syncthreads();

    int tx = tid & 15, ty = tid >> 4;
    int s0 = ty * 2;                 // 2 consecutive s-locals
    ull acc[2][2][4];                // [parity][ss][j], j: o = 2tx,2tx+1,2tx+32,2tx+33
#pragma unroll
    for (int p = 0; p < 2; p++)
#pragma unroll
        for (int a = 0; a < 2; a++)
#pragma unroll
            for (int c = 0; c < 4; c++) acc[p][a][c] = 0ull;

#pragma unroll
    for (int k = 0; k < MODES; ++k) {
        ulonglong2 tt = *(const ulonglong2*)&t2c[k][s0];          // (s0, s0+1)
        ulonglong2 g0 = *(const ulonglong2*)&gsh[k][2 * tx];      // o=2tx,2tx+1
        ulonglong2 g1 = *(const ulonglong2*)&gsh[k][2 * tx + 32]; // o=+32,+33
        const int par = k & 1;
        fma2(acc[par][0][0], tt.x, g0.x); fma2(acc[par][0][1], tt.x, g0.y);
        fma2(acc[par][0][2], tt.x, g1.x); fma2(acc[par][0][3], tt.x, g1.y);
        fma2(acc[par][1][0], tt.y, g0.x); fma2(acc[par][1][1], tt.y, g0.y);
        fma2(acc[par][1][2], tt.y, g1.x); fma2(acc[par][1][3], tt.y, g1.y);
    }

    float* ob = out + (size_t)b * S_TOT * COUT;
#pragma unroll
    for (int ss = 0; ss < 2; ++ss) {
        int s = q0 + 1 + s0 + ss;
        float* r0 = &ob[(size_t)s * COUT];
        float* r1 = &ob[(size_t)(2048 - s) * COUT];
        float* r2 = &ob[(size_t)(2048 + s) * COUT];
        float* r3 = &ob[(size_t)(4096 - s) * COUT];
#pragma unroll
        for (int g = 0; g < 2; ++g) {
            int j = 2 * g, o0 = 2 * tx + 32 * g;
            float2 Ea = unpk(acc[0][ss][j]),     Oa = unpk(acc[1][ss][j]);
            float2 Eb = unpk(acc[0][ss][j + 1]), Ob = unpk(acc[1][ss][j + 1]);
            *(float2*)&r0[o0] = make_float2(Ea.x + Ea.y + Oa.x + Oa.y,
                                            Eb.x + Eb.y + Ob.x + Ob.y);
            *(float2*)&r1[o0] = make_float2(Ea.x - Ea.y - Oa.x + Oa.y,
                                            Eb.x - Eb.y - Ob.x + Ob.y);
            *(float2*)&r2[o0] = make_float2(Ea.x + Ea.y - Oa.x - Oa.y,
                                            Eb.x + Eb.y - Ob.x - Ob.y);
            *(float2*)&r3[o0] = make_float2(Ea.x - Ea.y + Oa.x - Oa.y,
                                            Eb.x - Eb.y + Ob.x - Ob.y);
        }
    }

    // rows 0 and 2048 (sin terms vanish) — once per batch
    if (blockIdx.x == 0 && tid < COUT) {
        float a0 = 0.f, a1 = 0.f;
#pragma unroll
        for (int k = 0; k < MODES; ++k) {
            float gc = gsh[k][tid].x;
            a0 += gc;
            a1 += (k & 1) ? -gc : gc;
        }
        ob[tid] = a0;
        ob[(size_t)2048 * COUT + tid] = a1;
    }
}

extern "C" void kernel_launch(void* const* d_in, const int* in_sizes, int n_in,
                              void* d_out, int out_size) {
    const float* x = (const float*)d_in[0];   // [64, 4096, 64]
    const float* W = (const float*)d_in[1];   // [32, 64, 64]
    float* out = (float*)d_out;               // [64, 4096, 64]
    (void)in_sizes; (void)n_in; (void)out_size;

    twiddle_init<<<16, 256>>>();
    kA<<<dim3(CH_A, NB), 256>>>(x);
    kB<<<dim3(MODES, NB), 64>>>(W, x);
    kC<<<dim3(1024 / QPB_C, NB), 256>>>(out);
}

// round 7
// speedup vs baseline: 3.2042x; 1.0295x over previous
#include <cuda_runtime.h>

// SpectralConv1D: out = irfft( pad( rfft(x)[:, :32, :] @ W ) )
// Quad-folded trig transforms (4x via mirror symmetry over
// {s, 2048-s, 2048+s, 4096-s}). B=64, S=4096, Cin=Cout=64, MODES=32.
// kA: pipelined (double-buffered smem, 1 sync/stage).
// kC: twiddles by in-register complex recurrence (no twiddle smem reads).

#define S_TOT   4096
#define SMASK   4095
#define CIN     64
#define COUT    64
#define MODES   32
#define NB      64
#define CH_A    4
#define SUBS    4
#define NCH     (CH_A*SUBS)
#define QPB_A   256
#define STG_A   16
#define NSTG    (QPB_A/STG_A)
#define QPB_C   64

typedef unsigned long long ull;

__device__ float2 g_tw[S_TOT];                      // (cos,sin)(2*pi*j/4096)
__device__ float2 g_Yp[NCH][NB][MODES][CIN];        // split-K partials (Cr,Si)
__device__ float2 g_G[NB][MODES][COUT];             // mixed+scaled (Gc,Gs)

// ---- packed fp32x2 helpers ----
__device__ __forceinline__ ull pack2(float lo, float hi) {
    ull r; asm("mov.b64 %0, {%1, %2};" : "=l"(r) : "f"(lo), "f"(hi)); return r;
}
__device__ __forceinline__ float2 unpk(ull v) {
    float2 r; asm("mov.b64 {%0, %1}, %2;" : "=f"(r.x), "=f"(r.y) : "l"(v)); return r;
}
__device__ __forceinline__ void fma2(ull &acc, ull a, ull b) {
    asm("fma.rn.f32x2 %0, %1, %2, %0;" : "+l"(acc) : "l"(a), "l"(b));
}
__device__ __forceinline__ ull mul2(ull a, ull b) {
    ull r; asm("mul.rn.f32x2 %0, %1, %2;" : "=l"(r) : "l"(a), "l"(b)); return r;
}
__device__ __forceinline__ ull fma2r(ull a, ull b, ull c) {
    ull r; asm("fma.rn.f32x2 %0, %1, %2, %3;" : "=l"(r) : "l"(a), "l"(b), "l"(c)); return r;
}

__global__ void twiddle_init() {
    int j = blockIdx.x * blockDim.x + threadIdx.x;
    if (j < S_TOT) {
        float s, c;
        sincospif(j * (1.0f / 2048.0f), &s, &c);
        g_tw[j] = make_float2(c, s);
    }
}

// ---- Stage 1 (quad-folded forward DFT, pipelined) ----
// Cr_k += cos(th)*[P + (-1)^k Q],  Si_k += sin(th)*[R + (-1)^k T]
__global__ void __launch_bounds__(256, 2) kA(const float* __restrict__ x) {
    __shared__ float2 cmb[2][2][STG_A][CIN];  // [buf][parity][s][i], 32 KB
    __shared__ float2 t2[2][STG_A][MODES];    // 8 KB
    int b = blockIdx.y, tid = threadIdx.x;
    int tx  = tid & 15;        // i in {tx, tx+16, tx+32, tx+48}
    int kg  = (tid >> 4) & 3;  // k0 = kg*8
    int sub = tid >> 6;        // s-subset 0..3
    int k0 = kg * 8;
    int q00 = blockIdx.x * QPB_A;
    int r = tid >> 4, ig = tid & 15;   // loader role

    ull acc[8][4];
#pragma unroll
    for (int a = 0; a < 8; a++)
#pragma unroll
        for (int c = 0; c < 4; c++) acc[a][c] = 0ull;

    const float* xb = x + (size_t)b * S_TOT * CIN;

    float4 a1, a2, a3, a4;
    float2 tw0, tw1;
    {   // prologue: prefetch stage 0
        int s = q00 + 1 + r;
        a1 = *(const float4*)&xb[(size_t)s * CIN + ig * 4];
        a2 = *(const float4*)&xb[(size_t)(2048 - s) * CIN + ig * 4];
        a3 = *(const float4*)&xb[(size_t)(2048 + s) * CIN + ig * 4];
        a4 = *(const float4*)&xb[(size_t)(4096 - s) * CIN + ig * 4];
        int e0 = tid, e1 = tid + 256;
        tw0 = g_tw[((q00 + 1 + (e0 >> 5)) * (e0 & 31)) & SMASK];
        tw1 = g_tw[((q00 + 1 + (e1 >> 5)) * (e1 & 31)) & SMASK];
    }

    for (int st = 0; st < NSTG; ++st) {
        int buf = st & 1;
        int q0 = q00 + st * STG_A;
        {   // combine prefetched rows -> parity operands, store to smem
            int s = q0 + 1 + r;
            float h = (s == 1024) ? 0.5f : 1.0f;
            float x1[4] = {a1.x, a1.y, a1.z, a1.w};
            float x2[4] = {a2.x, a2.y, a2.z, a2.w};
            float x3[4] = {a3.x, a3.y, a3.z, a3.w};
            float x4[4] = {a4.x, a4.y, a4.z, a4.w};
            float pe[4], re[4], po[4], ro[4];
#pragma unroll
            for (int j = 0; j < 4; ++j) {
                float P = x1[j] + x4[j], Q = x2[j] + x3[j];
                float R = x1[j] - x4[j], T = x3[j] - x2[j];
                pe[j] = h * (P + Q); re[j] = h * (R + T);
                po[j] = h * (P - Q); ro[j] = h * (R - T);
            }
            *(float4*)&cmb[buf][0][r][ig * 4]     = make_float4(pe[0], re[0], pe[1], re[1]);
            *(float4*)&cmb[buf][0][r][ig * 4 + 2] = make_float4(pe[2], re[2], pe[3], re[3]);
            *(float4*)&cmb[buf][1][r][ig * 4]     = make_float4(po[0], ro[0], po[1], ro[1]);
            *(float4*)&cmb[buf][1][r][ig * 4 + 2] = make_float4(po[2], ro[2], po[3], ro[3]);
            int e0 = tid, e1 = tid + 256;
            t2[buf][e0 >> 5][e0 & 31] = tw0;
            t2[buf][e1 >> 5][e1 & 31] = tw1;
        }
        __syncthreads();
        if (st + 1 < NSTG) {   // prefetch next stage (overlaps compute below)
            int s = q0 + STG_A + 1 + r;
            a1 = *(const float4*)&xb[(size_t)s * CIN + ig * 4];
            a2 = *(const float4*)&xb[(size_t)(2048 - s) * CIN + ig * 4];
            a3 = *(const float4*)&xb[(size_t)(2048 + s) * CIN + ig * 4];
            a4 = *(const float4*)&xb[(size_t)(4096 - s) * CIN + ig * 4];
            int e0 = tid, e1 = tid + 256;
            tw0 = g_tw[((q0 + STG_A + 1 + (e0 >> 5)) * (e0 & 31)) & SMASK];
            tw1 = g_tw[((q0 + STG_A + 1 + (e1 >> 5)) * (e1 & 31)) & SMASK];
        }
#pragma unroll
        for (int slr = 0; slr < 4; ++slr) {
            int sl = sub * 4 + slr;
            ull cE[4], cO[4];
#pragma unroll
            for (int ii = 0; ii < 4; ++ii) {
                cE[ii] = *(const ull*)&cmb[buf][0][sl][tx + 16 * ii];
                cO[ii] = *(const ull*)&cmb[buf][1][sl][tx + 16 * ii];
            }
            ull tt[8];
#pragma unroll
            for (int m = 0; m < 4; ++m) {
                ulonglong2 tp = *(const ulonglong2*)&t2[buf][sl][k0 + 2 * m];
                tt[2 * m] = tp.x; tt[2 * m + 1] = tp.y;
            }
#pragma unroll
            for (int kk = 0; kk < 8; ++kk)
#pragma unroll
                for (int ii = 0; ii < 4; ++ii)
                    fma2(acc[kk][ii], tt[kk], (kk & 1) ? cO[ii] : cE[ii]);
        }
        // no second sync: STS(st+2) into this buf is separated from all
        // compute(st) reads by the barrier at stage st+1.
    }
    int ch = blockIdx.x * SUBS + sub;
#pragma unroll
    for (int kk = 0; kk < 8; ++kk)
#pragma unroll
        for (int ii = 0; ii < 4; ++ii)
            g_Yp[ch][b][k0 + kk][tx + 16 * ii] = unpk(acc[kk][ii]);
}

// ---- Stage 2: reduce partials + leftover rows {0,2048} + channel mix ----
__global__ void __launch_bounds__(64) kB(const float* __restrict__ W,
                                         const float* __restrict__ x) {
    int k = blockIdx.x, b = blockIdx.y, o = threadIdx.x;
    __shared__ float2 cs[CIN];
    {
        float2 a = make_float2(0.f, 0.f);
#pragma unroll
        for (int c = 0; c < NCH; ++c) {
            float2 v = g_Yp[c][b][k][o];
            a.x += v.x; a.y += v.y;
        }
        float x0    = x[(size_t)b * S_TOT * CIN + o];
        float x2048 = x[(size_t)b * S_TOT * CIN + 2048 * CIN + o];
        a.x += x0 + ((k & 1) ? -x2048 : x2048);
        cs[o] = a;
    }
    __syncthreads();
    const float* Wk = W + (size_t)k * CIN * COUT + o;
    float gc = 0.f, gs = 0.f;
#pragma unroll 8
    for (int i = 0; i < CIN; ++i) {
        float w = Wk[i * COUT];
        float2 v = cs[i];
        gc = fmaf(v.x, w, gc);
        gs = fmaf(v.y, w, gs);
    }
    float a = (k == 0 ? 1.0f : 2.0f) * (1.0f / (float)S_TOT);
    g_G[b][k][o] = make_float2(gc * a, gs * a);
}

// ---- Stage 3 (quad-folded inverse, register twiddle recurrence) ----
// Thread: 4 consecutive s, o in {2tx,2tx+1,2tx+32,2tx+33}; per k only the
// G operands come from smem (32B per k for 16 fma2).
__global__ void __launch_bounds__(256, 2) kC(float* __restrict__ out) {
    __shared__ float2 gsh[MODES][COUT];     // 16 KB
    int b = blockIdx.y, tid = threadIdx.x;
    int q0 = blockIdx.x * QPB_C;            // s = q0+1+..., 64 quads per block
    {   // copy G for this batch
        const ulonglong2* src = (const ulonglong2*)&g_G[b][0][0];
        ulonglong2* dst = (ulonglong2*)gsh;
#pragma unroll
        for (int t = 0; t < (MODES * COUT / 2) / 256; ++t)
            dst[tid + t * 256] = src[tid + t * 256];
    }
    __syncthreads();

    int tx = tid & 15, ty = tid >> 4;
    int sbase = q0 + 1 + ty * 4;            // 4 consecutive s
    // twiddle chains: W[j] = (cos,sin)(2pi k (sbase+j)/4096), start k=0
    ull Wc[4], Aj[4], Bj[4];
#pragma unroll
    for (int j = 0; j < 4; ++j) {
        float s1, c1;
        sincospif((float)(sbase + j) * (1.0f / 2048.0f), &s1, &c1);
        Aj[j] = pack2(c1, s1);
        Bj[j] = pack2(-s1, c1);
        Wc[j] = pack2(1.0f, 0.0f);
    }
    ull acc[2][4][4];                       // [parity][s][o]
#pragma unroll
    for (int p = 0; p < 2; p++)
#pragma unroll
        for (int a = 0; a < 4; a++)
#pragma unroll
            for (int c = 0; c < 4; c++) acc[p][a][c] = 0ull;

#pragma unroll
    for (int k = 0; k < MODES; ++k) {
        ulonglong2 g0 = *(const ulonglong2*)&gsh[k][2 * tx];      // o=2tx,2tx+1
        ulonglong2 g1 = *(const ulonglong2*)&gsh[k][2 * tx + 32]; // o=+32,+33
        ull gg[4] = {g0.x, g0.y, g1.x, g1.y};
        const int par = k & 1;
#pragma unroll
        for (int j = 0; j < 4; ++j)
#pragma unroll
            for (int o = 0; o < 4; ++o)
                fma2(acc[par][j][o], Wc[j], gg[o]);
        // step chains: W *= (c1, s1)
#pragma unroll
        for (int j = 0; j < 4; ++j) {
            float2 w = unpk(Wc[j]);
            ull t = mul2(pack2(w.x, w.x), Aj[j]);
            Wc[j] = fma2r(pack2(w.y, w.y), Bj[j], t);
        }
    }

    float* ob = out + (size_t)b * S_TOT * COUT;
#pragma unroll
    for (int ss = 0; ss < 4; ++ss) {
        int s = sbase + ss;
        float* r0 = &ob[(size_t)s * COUT];
        float* r1 = &ob[(size_t)(2048 - s) * COUT];
        float* r2 = &ob[(size_t)(2048 + s) * COUT];
        float* r3 = &ob[(size_t)(4096 - s) * COUT];
#pragma unroll
        for (int g = 0; g < 2; ++g) {
            int j = 2 * g, o0 = 2 * tx + 32 * g;
            float2 Ea = unpk(acc[0][ss][j]),     Oa = unpk(acc[1][ss][j]);
            float2 Eb = unpk(acc[0][ss][j + 1]), Ob = unpk(acc[1][ss][j + 1]);
            *(float2*)&r0[o0] = make_float2(Ea.x + Ea.y + Oa.x + Oa.y,
                                            Eb.x + Eb.y + Ob.x + Ob.y);
            *(float2*)&r1[o0] = make_float2(Ea.x - Ea.y - Oa.x + Oa.y,
                                            Eb.x - Eb.y - Ob.x + Ob.y);
            *(float2*)&r2[o0] = make_float2(Ea.x + Ea.y - Oa.x - Oa.y,
                                            Eb.x + Eb.y - Ob.x - Ob.y);
            *(float2*)&r3[o0] = make_float2(Ea.x - Ea.y + Oa.x - Oa.y,
                                            Eb.x - Eb.y + Ob.x - Ob.y);
        }
    }

    // rows 0 and 2048 (sin terms vanish) — once per batch
    if (blockIdx.x == 0 && tid < COUT) {
        float a0 = 0.f, a1 = 0.f;
#pragma unroll
        for (int k = 0; k < MODES; ++k) {
            float gc = gsh[k][tid].x;
            a0 += gc;
            a1 += (k & 1) ? -gc : gc;
        }
        ob[tid] = a0;
        ob[(size_t)2048 * COUT + tid] = a1;
    }
}

extern "C" void kernel_launch(void* const* d_in, const int* in_sizes, int n_in,
                              void* d_out, int out_size) {
    const float* x = (const float*)d_in[0];   // [64, 4096, 64]
    const float* W = (const float*)d_in[1];   // [32, 64, 64]
    float* out = (float*)d_out;               // [64, 4096, 64]
    (void)in_sizes; (void)n_in; (void)out_size;

    twiddle_init<<<16, 256>>>();
    kA<<<dim3(CH_A, NB), 256>>>(x);
    kB<<<dim3(MODES, NB), 64>>>(W, x);
    kC<<<dim3(1024 / QPB_C, NB), 256>>>(out);
}